// round 15
// baseline (speedup 1.0000x reference)
#include <cuda_runtime.h>
#include <cuda_fp16.h>
#include <math.h>

#define NN 10000
#define EE 160000
#define CC 64
#define RMAXF 5.0f
#define NPB 16
#define TPW_PAD 584
#define AGG_BLKS 625
#define UPD_BLKS 157

#define GEOM_BLKS 1250
#define EMB_BLKS  5000
#define PREP_BLKS 672
#define SETUP_BLKS (GEOM_BLKS + EMB_BLKS + PREP_BLKS)

// ---------------- device scratch ----------------
__device__ float4 d_vec[EE];
__device__ float d_sh12[EE * 12];
__device__ __half d_zh[2][EE * 16];
__device__ unsigned char d_act[EE];
__device__ int   d_count[NN];
__device__ int   d_offs[NN + 1];
__device__ int   d_cursor[NN];
__device__ int   d_ssnd[EE];
__device__ int   d_done[2];
__device__ float d_hup[NN * CC];
__device__ __half d_hh[NN * CC];
__device__ __half d_aggh[NN * 576];
__device__ __half d_W2T[2][576 * 16];
__device__ __half d_BT[2][64 * 640];
__device__ __half d_WupT[64 * 64];

__device__ __forceinline__ void mma16816(float& c0, float& c1, float& c2, float& c3,
                                         unsigned a0, unsigned a1, unsigned a2, unsigned a3,
                                         unsigned b0, unsigned b1) {
    asm volatile(
        "mma.sync.aligned.m16n8k16.row.col.f32.f16.f16.f32 "
        "{%0,%1,%2,%3},{%4,%5,%6,%7},{%8,%9},{%0,%1,%2,%3};\n"
        : "+f"(c0), "+f"(c1), "+f"(c2), "+f"(c3)
        : "r"(a0), "r"(a1), "r"(a2), "r"(a3), "r"(b0), "r"(b1));
}

// ---------------- fused setup ----------------
__device__ __forceinline__ void geom1_edge(int e, const float* __restrict__ pos,
                                           const float* __restrict__ shifts,
                                           const int* __restrict__ ei) {
    int s  = ei[e];
    int rv = ei[EE + e];
    float vx = pos[rv * 3 + 0] - pos[s * 3 + 0] + shifts[e * 3 + 0];
    float vy = pos[rv * 3 + 1] - pos[s * 3 + 1] + shifts[e * 3 + 1];
    float vz = pos[rv * 3 + 2] - pos[s * 3 + 2] + shifts[e * 3 + 2];
    float r = sqrtf(vx * vx + vy * vy + vz * vz) + 1e-9f;
    bool act = (r < RMAXF);
    d_act[e] = act ? 1 : 0;
    if (!act) return;
    atomicAdd(&d_count[rv], 1);
    d_vec[e] = make_float4(vx, vy, vz, r);
}

__global__ __launch_bounds__(128) void k_setup(const float* __restrict__ pos,
        const float* __restrict__ shifts, const int* __restrict__ ei,
        const float* __restrict__ na, const float* __restrict__ We,
        const float* __restrict__ ae, const float* __restrict__ Wup,
        const float* __restrict__ Wmix, const float* __restrict__ Wself,
        const float* __restrict__ Wr2, float* __restrict__ out) {
    int b = blockIdx.x, tid = threadIdx.x;
    if (b < GEOM_BLKS) {
        int e0 = b * 128 + tid;
        if (e0 < EE) geom1_edge(e0, pos, shifts, ei);
    } else if (b < GEOM_BLKS + EMB_BLKS) {
        __shared__ float hs[128];
        int slot = tid >> 6, c = tid & 63;
        int n = (b - GEOM_BLKS) * 2 + slot;
        float acc = 0.f;
#pragma unroll
        for (int k = 0; k < 10; k++) acc = fmaf(na[n * 10 + k], We[k * 64 + c], acc);
        hs[tid] = acc;
        d_hh[n * 64 + c] = __float2half(acc);
        if (c == 0) {
            float r = 0.f;
#pragma unroll
            for (int k = 0; k < 10; k++) r = fmaf(na[n * 10 + k], ae[k], r);
            out[n] = r;
        }
        __syncthreads();
        float hu = 0.f;
#pragma unroll
        for (int k = 0; k < 64; k++) hu = fmaf(hs[slot * 64 + k], Wup[k * 64 + c], hu);
        d_hup[n * 64 + c] = hu;
    } else {
        int i = (b - GEOM_BLKS - EMB_BLKS) * 128 + tid;
        if (i < 81920) {
            int t = i / 40960, r = i - t * 40960, n = r / 640, k = r - n * 640;
            float v = (k < 576) ? Wmix[t * 36864 + k * 64 + n]
                                : Wself[t * 4096 + (k - 576) * 64 + n];
            d_BT[t][r] = __float2half(v);
        } else if (i < 86016) {
            int q = i - 81920;
            int o = q >> 6, ii = q & 63;
            d_WupT[q] = __float2half(Wup[4096 + ii * 64 + o]);
        }
        int j = i;
        if (j < 2 * 9216) {
            int t = j / 9216, r = j - t * 9216, cg = r >> 4, m = r & 15;
            d_W2T[t][r] = __float2half(Wr2[t * 9216 + m * 576 + cg]);
        }
    }
}

// ---------------- single-kernel scan ----------------
__global__ __launch_bounds__(1024) void k_scan() {
    __shared__ int ws[32];
    __shared__ int tot_s;
    int t = threadIdx.x, lane = t & 31, w = t >> 5;
    if (t == 0) { d_done[0] = 0; d_done[1] = 0; }
    int run = 0;
    for (int rr = 0; rr < 10; rr++) {
        int idx = rr * 1024 + t;
        int v = 0;
        if (idx < NN) { v = d_count[idx]; d_count[idx] = 0; }
        int inc = v;
#pragma unroll
        for (int o = 1; o < 32; o <<= 1) {
            int u = __shfl_up_sync(0xffffffffu, inc, o);
            if (lane >= o) inc += u;
        }
        if (lane == 31) ws[w] = inc;
        __syncthreads();
        if (w == 0) {
            int x = ws[lane];
            int xi = x;
#pragma unroll
            for (int o = 1; o < 32; o <<= 1) {
                int u = __shfl_up_sync(0xffffffffu, xi, o);
                if (lane >= o) xi += u;
            }
            ws[lane] = xi - x;
            if (lane == 31) tot_s = xi;
        }
        __syncthreads();
        int excl = run + ws[w] + inc - v;
        if (idx < NN) { d_offs[idx] = excl; d_cursor[idx] = excl; }
        run += tot_s;
        __syncthreads();
    }
    if (t == 0) d_offs[NN] = run;
}

// ---------------- fused scatter + heavy geometry ----------------
__global__ __launch_bounds__(128) void k_scatgeo(const int* __restrict__ ei,
                                                 const float* __restrict__ Wr1) {
    __shared__ float Ws[256];
    Ws[threadIdx.x] = Wr1[threadIdx.x];
    Ws[threadIdx.x + 128] = Wr1[threadIdx.x + 128];
    __syncthreads();
    int e = blockIdx.x * 128 + threadIdx.x;
    if (e >= EE || !d_act[e]) return;
    int rv = ei[EE + e];
    int p = atomicAdd(&d_cursor[rv], 1);
    d_ssnd[p] = ei[e];

    float4 v = d_vec[e];
    float r = v.w;
    float inv = __fdividef(1.0f, r);
    float ux = v.x * inv, uy = v.y * inv, uz = v.z * inv;
    const float s3 = 1.7320508075688772f, s5 = 2.2360679774997896f, s15 = 3.872983346207417f;
    float4 fA = make_float4(1.0f, s3 * ux, s3 * uy, s3 * uz);
    float4 fB = make_float4(s15 * ux * uy, s15 * uy * uz,
                            0.5f * s5 * (3.0f * uz * uz - 1.0f), s15 * ux * uz);
    float4 fC = make_float4(0.5f * s15 * (ux * ux - uy * uy), 0.f, 0.f, 0.f);
    float4* shp = (float4*)&d_sh12[(long)p * 12];
    shp[0] = fA; shp[1] = fB; shp[2] = fC;

    float xx = r * (1.0f / RMAXF);
    float th = 3.14159265358979323846f * xx;
    float s1, c1;
    __sincosf(th, &s1, &c1);
    float x2 = xx * xx;
    float x6 = x2 * x2 * x2;
    float fc = 1.0f + x6 * (-28.0f + xx * (48.0f - 21.0f * xx));
    float pref = 0.6324555320336759f * inv * fc;
    float ef[8];
    float sp = 0.0f, sc = s1, c2 = 2.0f * c1;
#pragma unroll
    for (int n = 0; n < 8; n++) {
        ef[n] = pref * sc;
        float nx = c2 * sc - sp;
        sp = sc; sc = nx;
    }
#pragma unroll
    for (int t = 0; t < 2; t++) {
        float a[16];
#pragma unroll
        for (int m = 0; m < 16; m++) {
            float acc = 0.f;
#pragma unroll
            for (int n = 0; n < 8; n++) acc = fmaf(ef[n], Ws[t * 128 + n * 16 + m], acc);
            a[m] = __fdividef(acc, 1.0f + __expf(-acc));
        }
        __half2 hz[8];
#pragma unroll
        for (int q = 0; q < 8; q++) hz[q] = __floats2half2_rn(a[2 * q], a[2 * q + 1]);
        uint4* zp = (uint4*)&d_zh[t][(long)p * 16];
        zp[0] = *(uint4*)&hz[0];
        zp[1] = *(uint4*)&hz[4];
    }
}

// ---------------- smem overlays ----------------
struct AggSmem {
    float tpwS[16][TPW_PAD];
    float hupS[16][64];
    __half zS[2][16][16];
    float shS[2][16][12];
    int sndS[2][16];
    int offsS[NPB + 1];
};
struct UpdSmem {
    __half As[2][64][16];
    __half BsT[2][64][16];
    __half hS[64][72];
    __half WuS[64 * 64];
};

// ---------------- agg body (round-11, unchanged math) ----------------
template<int SOFF, int SCNT>
__device__ __forceinline__ void agg_core(int tid, int c, int n0,
        const __half* __restrict__ zg,
        const unsigned* Bf0, const unsigned* Bf1, AggSmem* sa) {
    int lane = tid & 31, w = tid >> 5;
    int ar = lane >> 2, ak = (lane & 3) * 2;
    int iBeg = sa->offsS[0], iEnd = sa->offsS[NPB];
    int nChunks = (iEnd - iBeg + 15) >> 4;
    int kn = 0, nextb = sa->offsS[1];
    float acc[SCNT];
#pragma unroll
    for (int j = 0; j < SCNT; j++) acc[j] = 0.f;

    int zE = tid >> 1, zP = tid & 1;
    int shI = tid - 32, shE = shI / 3, shP = shI - shE * 3;
    int snE = tid - 80;
    int hE = tid >> 3, hQ = tid & 7;

    if (nChunks > 0) {
        long basec = iBeg;
        if (tid < 32) {
            long idx = basec + zE; if (idx > iEnd - 1) idx = iEnd - 1;
            *(uint4*)&sa->zS[0][zE][zP * 8] = *(const uint4*)&zg[idx * 16 + zP * 8];
        } else if (tid < 80) {
            long idx = basec + shE; if (idx > iEnd - 1) idx = iEnd - 1;
            *(float4*)&sa->shS[0][shE][shP * 4] = *(const float4*)&d_sh12[idx * 12 + shP * 4];
        } else if (tid < 96) {
            long idx = basec + snE; if (idx > iEnd - 1) idx = iEnd - 1;
            sa->sndS[0][snE] = d_ssnd[idx];
        }
    }
    __syncthreads();

    int cur = 0;
    for (int k = 0; k < nChunks; k++) {
        int base = iBeg + k * 16;
        int cnt = min(16, iEnd - base);
        int nxt = cur ^ 1;
        uint4 zreg; float4 shreg; int snreg = 0;
        bool hasNext = (k + 1 < nChunks);
        if (hasNext) {
            long b2 = base + 16;
            if (tid < 32) {
                long idx = b2 + zE; if (idx > iEnd - 1) idx = iEnd - 1;
                zreg = *(const uint4*)&zg[idx * 16 + zP * 8];
            } else if (tid < 80) {
                long idx = b2 + shE; if (idx > iEnd - 1) idx = iEnd - 1;
                shreg = *(const float4*)&d_sh12[idx * 12 + shP * 4];
            } else if (tid < 96) {
                long idx = b2 + snE; if (idx > iEnd - 1) idx = iEnd - 1;
                snreg = d_ssnd[idx];
            }
        }
        int sn = (hE < cnt) ? sa->sndS[cur][hE] : 0;
        const float4* hp = (const float4*)&d_hup[sn * 64 + hQ * 8];
        float4 h0 = hp[0], h1 = hp[1];

        unsigned A0 = *(const unsigned*)&sa->zS[cur][ar][ak];
        unsigned A1 = *(const unsigned*)&sa->zS[cur][ar + 8][ak];
        unsigned A2 = *(const unsigned*)&sa->zS[cur][ar][ak + 8];
        unsigned A3 = *(const unsigned*)&sa->zS[cur][ar + 8][ak + 8];
#pragma unroll
        for (int q = 0; q < 18; q++) {
            int cb = (w * 18 + q) * 8;
            float c0 = 0.f, c1 = 0.f, c2 = 0.f, c3 = 0.f;
            mma16816(c0, c1, c2, c3, A0, A1, A2, A3, Bf0[q], Bf1[q]);
            int cg0 = cb + 2 * (lane & 3);
            *(float2*)&sa->tpwS[ar][cg0]     = make_float2(c0, c1);
            *(float2*)&sa->tpwS[ar + 8][cg0] = make_float2(c2, c3);
        }
        *(float4*)&sa->hupS[hE][hQ * 8] = h0;
        *(float4*)&sa->hupS[hE][hQ * 8 + 4] = h1;
        if (hasNext) {
            if (tid < 32)      *(uint4*)&sa->zS[nxt][zE][zP * 8] = zreg;
            else if (tid < 80) *(float4*)&sa->shS[nxt][shE][shP * 4] = shreg;
            else if (tid < 96) sa->sndS[nxt][snE] = snreg;
        }
        __syncthreads();

        for (int e = 0; e < cnt; e++) {
            int i = base + e;
            while (i >= nextb) {
#pragma unroll
                for (int j = 0; j < SCNT; j++)
                    d_aggh[(long)(n0 + kn) * 576 + c * 9 + SOFF + j] =
                        __float2half(acc[j] * (1.0f / 32.0f));
#pragma unroll
                for (int j = 0; j < SCNT; j++) acc[j] = 0.f;
                kn++;
                nextb = (kn < NPB) ? sa->offsS[kn + 1] : 0x7fffffff;
            }
            float hv = sa->hupS[e][c];
#pragma unroll
            for (int j = 0; j < SCNT; j++)
                acc[j] = fmaf(hv * sa->shS[cur][e][SOFF + j], sa->tpwS[e][c * 9 + SOFF + j], acc[j]);
        }
        __syncthreads();
        cur = nxt;
    }
    while (kn < NPB) {
#pragma unroll
        for (int j = 0; j < SCNT; j++)
            d_aggh[(long)(n0 + kn) * 576 + c * 9 + SOFF + j] =
                __float2half(acc[j] * (1.0f / 32.0f));
#pragma unroll
        for (int j = 0; j < SCNT; j++) acc[j] = 0.f;
        kn++;
    }
}

// ---------------- fused layer kernel: agg blocks + spin-gated update blocks ----------------
__global__ __launch_bounds__(128) void k_layer(int t, const float* __restrict__ wread,
                                               const float* __restrict__ Wmlp1,
                                               const float* __restrict__ wmlp2,
                                               float* __restrict__ out) {
    __shared__ __align__(16) unsigned char smraw[sizeof(AggSmem)];
    int tid = threadIdx.x, lane = tid & 31, w = tid >> 5;

    if (blockIdx.x < AGG_BLKS) {
        // ---- aggregation role ----
        AggSmem* sa = (AggSmem*)smraw;
        int n0 = blockIdx.x * NPB;
        if (tid < NPB + 1) sa->offsS[tid] = d_offs[n0 + tid];
        const __half* W2 = d_W2T[t];
        unsigned Bf0[18], Bf1[18];
        int ar = lane >> 2, ak = (lane & 3) * 2;
#pragma unroll
        for (int q = 0; q < 18; q++) {
            int cb = (w * 18 + q) * 8;
            Bf0[q] = *(const unsigned*)&W2[(cb + ar) * 16 + ak];
            Bf1[q] = *(const unsigned*)&W2[(cb + ar) * 16 + ak + 8];
        }
        __syncthreads();
        const __half* zg = d_zh[t];
        int c = tid & 63;
        if (tid < 64) agg_core<0, 5>(tid, c, n0, zg, Bf0, Bf1, sa);
        else          agg_core<5, 4>(tid, c, n0, zg, Bf0, Bf1, sa);
        __threadfence();
        __syncthreads();
        if (tid == 0) atomicAdd(&d_done[t], 1);
        return;
    }

    // ---- update role: wait for all agg blocks ----
    if (tid == 0) {
        while (atomicAdd(&d_done[t], 0) < AGG_BLKS) __nanosleep(256);
    }
    __syncthreads();
    __threadfence();

    UpdSmem* su = (UpdSmem*)smraw;
    int m0 = (blockIdx.x - AGG_BLKS) * 64;
    float C[8][4];
#pragma unroll
    for (int j = 0; j < 8; j++)
#pragma unroll
        for (int i = 0; i < 4; i++) C[j][i] = 0.f;

    int r = tid >> 1, hf = tid & 1;
    int node = m0 + r;
    int arf = 16 * w + (lane >> 2), akf = (lane & 3) * 2;

    {
        uint4 av = make_uint4(0, 0, 0, 0);
        if (node < NN) av = ((const uint4*)&d_aggh[(long)node * 576])[hf];
        uint4 bv = ((const uint4*)&d_BT[t][r * 640])[hf];
        *(uint4*)&su->As[0][r][hf * 8] = av;
        *(uint4*)&su->BsT[0][r][hf * 8] = bv;
    }
    __syncthreads();

    int cur = 0;
    for (int step = 0; step < 40; step++) {
        uint4 av, bv;
        bool hasNext = (step < 39);
        if (hasNext) {
            int k0 = (step + 1) * 16;
            av = make_uint4(0, 0, 0, 0);
            if (node < NN) {
                const uint4* ap = (k0 < 576) ? (const uint4*)&d_aggh[(long)node * 576 + k0]
                                             : (const uint4*)&d_hh[node * 64 + (k0 - 576)];
                av = ap[hf];
            }
            bv = *((const uint4*)&d_BT[t][r * 640 + k0] + hf);
        }
        unsigned A0 = *(const unsigned*)&su->As[cur][arf][akf];
        unsigned A1 = *(const unsigned*)&su->As[cur][arf + 8][akf];
        unsigned A2 = *(const unsigned*)&su->As[cur][arf][akf + 8];
        unsigned A3 = *(const unsigned*)&su->As[cur][arf + 8][akf + 8];
#pragma unroll
        for (int j = 0; j < 8; j++) {
            int bn = j * 8 + (lane >> 2);
            unsigned B0 = *(const unsigned*)&su->BsT[cur][bn][akf];
            unsigned B1 = *(const unsigned*)&su->BsT[cur][bn][akf + 8];
            mma16816(C[j][0], C[j][1], C[j][2], C[j][3], A0, A1, A2, A3, B0, B1);
        }
        if (hasNext) {
            *(uint4*)&su->As[cur ^ 1][r][hf * 8] = av;
            *(uint4*)&su->BsT[cur ^ 1][r][hf * 8] = bv;
            __syncthreads();
            cur ^= 1;
        }
    }
    __syncthreads();
    {
        int ac = 2 * (lane & 3);
#pragma unroll
        for (int j = 0; j < 8; j++) {
            *(__half2*)&su->hS[arf][j * 8 + ac]     = __floats2half2_rn(C[j][0], C[j][1]);
            *(__half2*)&su->hS[arf + 8][j * 8 + ac] = __floats2half2_rn(C[j][2], C[j][3]);
        }
    }
    __syncthreads();

    if (t == 0) {
        for (int i = tid; i < 64 * 32; i += 128) {
            int rr = i >> 5, cc2 = i & 31;
            if (m0 + rr < NN)
                ((__half2*)&d_hh[(m0 + rr) * 64])[cc2] = *(__half2*)&su->hS[rr][cc2 * 2];
        }
        if (tid < 64 && m0 + tid < NN) {
            float acc = 0.f;
#pragma unroll
            for (int k2 = 0; k2 < 64; k2++)
                acc = fmaf(__half2float(su->hS[tid][k2]), wread[k2], acc);
            out[NN + m0 + tid] = acc;
        }
        {
            const uint4* src = (const uint4*)d_WupT;
            uint4* dst = (uint4*)su->WuS;
#pragma unroll
            for (int i = 0; i < 4; i++) dst[tid + i * 128] = src[tid + i * 128];
        }
        __syncthreads();
        float H[8][4];
#pragma unroll
        for (int j = 0; j < 8; j++)
#pragma unroll
            for (int i = 0; i < 4; i++) H[j][i] = 0.f;
#pragma unroll
        for (int s = 0; s < 4; s++) {
            int k0 = s * 16;
            unsigned A0 = *(const unsigned*)&su->hS[arf][k0 + akf];
            unsigned A1 = *(const unsigned*)&su->hS[arf + 8][k0 + akf];
            unsigned A2 = *(const unsigned*)&su->hS[arf][k0 + akf + 8];
            unsigned A3 = *(const unsigned*)&su->hS[arf + 8][k0 + akf + 8];
#pragma unroll
            for (int j = 0; j < 8; j++) {
                int bn = j * 8 + (lane >> 2);
                unsigned B0 = *(const unsigned*)&su->WuS[bn * 64 + k0 + akf];
                unsigned B1 = *(const unsigned*)&su->WuS[bn * 64 + k0 + akf + 8];
                mma16816(H[j][0], H[j][1], H[j][2], H[j][3], A0, A1, A2, A3, B0, B1);
            }
        }
        int ac = 2 * (lane & 3);
#pragma unroll
        for (int j = 0; j < 8; j++) {
            int col = j * 8 + ac;
            if (m0 + arf < NN) {
                d_hup[(m0 + arf) * 64 + col] = H[j][0];
                d_hup[(m0 + arf) * 64 + col + 1] = H[j][1];
            }
            if (m0 + arf + 8 < NN) {
                d_hup[(m0 + arf + 8) * 64 + col] = H[j][2];
                d_hup[(m0 + arf + 8) * 64 + col + 1] = H[j][3];
            }
        }
    } else {
        int nd = tid >> 1, hf2 = tid & 1;
        float y[8];
#pragma unroll
        for (int o = 0; o < 8; o++) y[o] = 0.f;
        for (int k2 = 0; k2 < 64; k2++) {
            float hv = __half2float(su->hS[nd][k2]);
#pragma unroll
            for (int o = 0; o < 8; o++)
                y[o] = fmaf(hv, Wmlp1[k2 * 16 + hf2 * 8 + o], y[o]);
        }
        float acc = 0.f;
#pragma unroll
        for (int o = 0; o < 8; o++) {
            float s2 = __fdividef(y[o], 1.0f + __expf(-y[o]));
            acc = fmaf(s2, wmlp2[hf2 * 8 + o], acc);
        }
        acc += __shfl_xor_sync(0xffffffffu, acc, 1);
        if (hf2 == 0 && m0 + nd < NN) out[2 * NN + m0 + nd] = acc;
    }
}

// ---------------- host launch ----------------
extern "C" void kernel_launch(void* const* d_in, const int* in_sizes, int n_in,
                              void* d_out, int out_size) {
    const float *positions = nullptr, *node_attrs = nullptr, *shifts = nullptr;
    const float *atomic_energies = nullptr, *W_embed = nullptr, *W_up = nullptr;
    const float *W_r1 = nullptr, *W_r2 = nullptr, *W_mix = nullptr, *W_self = nullptr;
    const float *w_read = nullptr, *W_mlp1 = nullptr, *w_mlp2 = nullptr;
    const int* edge_index = nullptr;
    for (int i = 0; i < n_in; i++) {
        switch (in_sizes[i]) {
            case 30000:  positions = (const float*)d_in[i]; break;
            case 100000: node_attrs = (const float*)d_in[i]; break;
            case 480000: shifts = (const float*)d_in[i]; break;
            case 320000: edge_index = (const int*)d_in[i]; break;
            case 10:     atomic_energies = (const float*)d_in[i]; break;
            case 640:    W_embed = (const float*)d_in[i]; break;
            case 8192:   if (!W_up) W_up = (const float*)d_in[i];
                         else W_self = (const float*)d_in[i]; break;
            case 256:    W_r1 = (const float*)d_in[i]; break;
            case 18432:  W_r2 = (const float*)d_in[i]; break;
            case 73728:  W_mix = (const float*)d_in[i]; break;
            case 64:     w_read = (const float*)d_in[i]; break;
            case 1024:   W_mlp1 = (const float*)d_in[i]; break;
            case 16:     w_mlp2 = (const float*)d_in[i]; break;
            default: break;
        }
    }
    float* out = (float*)d_out;
    (void)out_size;

    k_setup<<<SETUP_BLKS, 128>>>(positions, shifts, edge_index, node_attrs, W_embed,
                                 atomic_energies, W_up, W_mix, W_self, W_r2, out);
    k_scan<<<1, 1024>>>();
    k_scatgeo<<<(EE + 127) / 128, 128>>>(edge_index, W_r1);

    for (int t = 0; t < 2; t++)
        k_layer<<<AGG_BLKS + UPD_BLKS, 128>>>(t, w_read, W_mlp1, w_mlp2, out);
}

// round 16
// speedup vs baseline: 1.1157x; 1.1157x over previous
#include <cuda_runtime.h>
#include <cuda_fp16.h>
#include <math.h>

#define NN 10000
#define EE 160000
#define CC 64
#define RMAXF 5.0f
#define NPB 16
#define TPW_PAD 584

#define GEOM_BLKS 1250
#define EMB_BLKS  5000
#define PREP_BLKS 672
#define SETUP_BLKS (GEOM_BLKS + EMB_BLKS + PREP_BLKS)

// ---------------- device scratch ----------------
__device__ float4 d_vec[EE];
__device__ float d_sh12[EE * 12];
__device__ __half d_zh[2][EE * 16];
__device__ unsigned char d_act[EE];
__device__ int   d_count[NN];
__device__ int   d_offs[NN + 1];
__device__ int   d_cursor[NN];
__device__ int   d_ssnd[EE];
__device__ float d_hup[NN * CC];
__device__ __half d_hh[NN * CC];
__device__ __half d_aggh[NN * 576];
__device__ __half d_W2T[2][576 * 16];
__device__ __half d_BT[2][64 * 640];
__device__ __half d_WupT[64 * 64];

__device__ __forceinline__ void mma16816(float& c0, float& c1, float& c2, float& c3,
                                         unsigned a0, unsigned a1, unsigned a2, unsigned a3,
                                         unsigned b0, unsigned b1) {
    asm volatile(
        "mma.sync.aligned.m16n8k16.row.col.f32.f16.f16.f32 "
        "{%0,%1,%2,%3},{%4,%5,%6,%7},{%8,%9},{%0,%1,%2,%3};\n"
        : "+f"(c0), "+f"(c1), "+f"(c2), "+f"(c3)
        : "r"(a0), "r"(a1), "r"(a2), "r"(a3), "r"(b0), "r"(b1));
}

// ---------------- fused setup ----------------
__device__ __forceinline__ void geom1_edge(int e, const float* __restrict__ pos,
                                           const float* __restrict__ shifts,
                                           const int* __restrict__ ei) {
    int s  = ei[e];
    int rv = ei[EE + e];
    float vx = pos[rv * 3 + 0] - pos[s * 3 + 0] + shifts[e * 3 + 0];
    float vy = pos[rv * 3 + 1] - pos[s * 3 + 1] + shifts[e * 3 + 1];
    float vz = pos[rv * 3 + 2] - pos[s * 3 + 2] + shifts[e * 3 + 2];
    float r = sqrtf(vx * vx + vy * vy + vz * vz) + 1e-9f;
    bool act = (r < RMAXF);
    d_act[e] = act ? 1 : 0;
    if (!act) return;
    atomicAdd(&d_count[rv], 1);
    d_vec[e] = make_float4(vx, vy, vz, r);
}

__global__ __launch_bounds__(128) void k_setup(const float* __restrict__ pos,
        const float* __restrict__ shifts, const int* __restrict__ ei,
        const float* __restrict__ na, const float* __restrict__ We,
        const float* __restrict__ ae, const float* __restrict__ Wup,
        const float* __restrict__ Wmix, const float* __restrict__ Wself,
        const float* __restrict__ Wr2, float* __restrict__ out) {
    int b = blockIdx.x, tid = threadIdx.x;
    if (b < GEOM_BLKS) {
        int e0 = b * 128 + tid;
        if (e0 < EE) geom1_edge(e0, pos, shifts, ei);
    } else if (b < GEOM_BLKS + EMB_BLKS) {
        __shared__ float hs[128];
        int slot = tid >> 6, c = tid & 63;
        int n = (b - GEOM_BLKS) * 2 + slot;
        float acc = 0.f;
#pragma unroll
        for (int k = 0; k < 10; k++) acc = fmaf(na[n * 10 + k], We[k * 64 + c], acc);
        hs[tid] = acc;
        d_hh[n * 64 + c] = __float2half(acc);
        if (c == 0) {
            float r = 0.f;
#pragma unroll
            for (int k = 0; k < 10; k++) r = fmaf(na[n * 10 + k], ae[k], r);
            out[n] = r;
        }
        __syncthreads();
        float hu = 0.f;
#pragma unroll
        for (int k = 0; k < 64; k++) hu = fmaf(hs[slot * 64 + k], Wup[k * 64 + c], hu);
        d_hup[n * 64 + c] = hu;
    } else {
        int i = (b - GEOM_BLKS - EMB_BLKS) * 128 + tid;
        if (i < 81920) {
            int t = i / 40960, r = i - t * 40960, n = r / 640, k = r - n * 640;
            float v = (k < 576) ? Wmix[t * 36864 + k * 64 + n]
                                : Wself[t * 4096 + (k - 576) * 64 + n];
            d_BT[t][r] = __float2half(v);
        } else if (i < 86016) {
            int q = i - 81920;
            int o = q >> 6, ii = q & 63;
            d_WupT[q] = __float2half(Wup[4096 + ii * 64 + o]);
        }
        int j = i;
        if (j < 2 * 9216) {
            int t = j / 9216, r = j - t * 9216, cg = r >> 4, m = r & 15;
            d_W2T[t][r] = __float2half(Wr2[t * 9216 + m * 576 + cg]);
        }
    }
}

// ---------------- single-kernel scan ----------------
__global__ __launch_bounds__(1024) void k_scan() {
    __shared__ int ws[32];
    __shared__ int tot_s;
    int t = threadIdx.x, lane = t & 31, w = t >> 5;
    int run = 0;
    for (int rr = 0; rr < 10; rr++) {
        int idx = rr * 1024 + t;
        int v = 0;
        if (idx < NN) { v = d_count[idx]; d_count[idx] = 0; }
        int inc = v;
#pragma unroll
        for (int o = 1; o < 32; o <<= 1) {
            int u = __shfl_up_sync(0xffffffffu, inc, o);
            if (lane >= o) inc += u;
        }
        if (lane == 31) ws[w] = inc;
        __syncthreads();
        if (w == 0) {
            int x = ws[lane];
            int xi = x;
#pragma unroll
            for (int o = 1; o < 32; o <<= 1) {
                int u = __shfl_up_sync(0xffffffffu, xi, o);
                if (lane >= o) xi += u;
            }
            ws[lane] = xi - x;
            if (lane == 31) tot_s = xi;
        }
        __syncthreads();
        int excl = run + ws[w] + inc - v;
        if (idx < NN) { d_offs[idx] = excl; d_cursor[idx] = excl; }
        run += tot_s;
        __syncthreads();
    }
    if (t == 0) d_offs[NN] = run;
}

// ---------------- fused scatter + heavy geometry ----------------
__global__ __launch_bounds__(128) void k_scatgeo(const int* __restrict__ ei,
                                                 const float* __restrict__ Wr1) {
    __shared__ float Ws[256];
    Ws[threadIdx.x] = Wr1[threadIdx.x];
    Ws[threadIdx.x + 128] = Wr1[threadIdx.x + 128];
    __syncthreads();
    int e = blockIdx.x * 128 + threadIdx.x;
    if (e >= EE || !d_act[e]) return;
    int rv = ei[EE + e];
    int p = atomicAdd(&d_cursor[rv], 1);
    d_ssnd[p] = ei[e];

    float4 v = d_vec[e];
    float r = v.w;
    float inv = __fdividef(1.0f, r);
    float ux = v.x * inv, uy = v.y * inv, uz = v.z * inv;
    const float s3 = 1.7320508075688772f, s5 = 2.2360679774997896f, s15 = 3.872983346207417f;
    float4 fA = make_float4(1.0f, s3 * ux, s3 * uy, s3 * uz);
    float4 fB = make_float4(s15 * ux * uy, s15 * uy * uz,
                            0.5f * s5 * (3.0f * uz * uz - 1.0f), s15 * ux * uz);
    float4 fC = make_float4(0.5f * s15 * (ux * ux - uy * uy), 0.f, 0.f, 0.f);
    float4* shp = (float4*)&d_sh12[(long)p * 12];
    shp[0] = fA; shp[1] = fB; shp[2] = fC;

    float xx = r * (1.0f / RMAXF);
    float th = 3.14159265358979323846f * xx;
    float s1, c1;
    __sincosf(th, &s1, &c1);
    float x2 = xx * xx;
    float x6 = x2 * x2 * x2;
    float fc = 1.0f + x6 * (-28.0f + xx * (48.0f - 21.0f * xx));
    float pref = 0.6324555320336759f * inv * fc;
    float ef[8];
    float sp = 0.0f, sc = s1, c2 = 2.0f * c1;
#pragma unroll
    for (int n = 0; n < 8; n++) {
        ef[n] = pref * sc;
        float nx = c2 * sc - sp;
        sp = sc; sc = nx;
    }
#pragma unroll
    for (int t = 0; t < 2; t++) {
        float a[16];
#pragma unroll
        for (int m = 0; m < 16; m++) {
            float acc = 0.f;
#pragma unroll
            for (int n = 0; n < 8; n++) acc = fmaf(ef[n], Ws[t * 128 + n * 16 + m], acc);
            a[m] = __fdividef(acc, 1.0f + __expf(-acc));
        }
        __half2 hz[8];
#pragma unroll
        for (int q = 0; q < 8; q++) hz[q] = __floats2half2_rn(a[2 * q], a[2 * q + 1]);
        uint4* zp = (uint4*)&d_zh[t][(long)p * 16];
        zp[0] = *(uint4*)&hz[0];
        zp[1] = *(uint4*)&hz[4];
    }
}

// ---------------- agg: pipelined MMA tp_w + scalar epilogue (round-11 best) ----------------
template<int SOFF, int SCNT>
__device__ __forceinline__ void agg_core(int tid, int c, int n0,
        const __half* __restrict__ zg,
        const unsigned* Bf0, const unsigned* Bf1,
        float (*tpwS)[TPW_PAD], float (*hupS)[64],
        __half (*zS)[16][16], float (*shS)[16][12], int (*sndS)[16],
        const int* offsS) {
    int lane = tid & 31, w = tid >> 5;
    int ar = lane >> 2, ak = (lane & 3) * 2;
    int iBeg = offsS[0], iEnd = offsS[NPB];
    int nChunks = (iEnd - iBeg + 15) >> 4;
    int kn = 0, nextb = offsS[1];
    float acc[SCNT];
#pragma unroll
    for (int j = 0; j < SCNT; j++) acc[j] = 0.f;

    int zE = tid >> 1, zP = tid & 1;
    int shI = tid - 32, shE = shI / 3, shP = shI - shE * 3;
    int snE = tid - 80;
    int hE = tid >> 3, hQ = tid & 7;

    if (nChunks > 0) {
        long basec = iBeg;
        if (tid < 32) {
            long idx = basec + zE; if (idx > iEnd - 1) idx = iEnd - 1;
            *(uint4*)&zS[0][zE][zP * 8] = *(const uint4*)&zg[idx * 16 + zP * 8];
        } else if (tid < 80) {
            long idx = basec + shE; if (idx > iEnd - 1) idx = iEnd - 1;
            *(float4*)&shS[0][shE][shP * 4] = *(const float4*)&d_sh12[idx * 12 + shP * 4];
        } else if (tid < 96) {
            long idx = basec + snE; if (idx > iEnd - 1) idx = iEnd - 1;
            sndS[0][snE] = d_ssnd[idx];
        }
    }
    __syncthreads();

    int cur = 0;
    for (int k = 0; k < nChunks; k++) {
        int base = iBeg + k * 16;
        int cnt = min(16, iEnd - base);
        int nxt = cur ^ 1;
        uint4 zreg; float4 shreg; int snreg = 0;
        bool hasNext = (k + 1 < nChunks);
        if (hasNext) {
            long b2 = base + 16;
            if (tid < 32) {
                long idx = b2 + zE; if (idx > iEnd - 1) idx = iEnd - 1;
                zreg = *(const uint4*)&zg[idx * 16 + zP * 8];
            } else if (tid < 80) {
                long idx = b2 + shE; if (idx > iEnd - 1) idx = iEnd - 1;
                shreg = *(const float4*)&d_sh12[idx * 12 + shP * 4];
            } else if (tid < 96) {
                long idx = b2 + snE; if (idx > iEnd - 1) idx = iEnd - 1;
                snreg = d_ssnd[idx];
            }
        }
        int sn = (hE < cnt) ? sndS[cur][hE] : 0;
        const float4* hp = (const float4*)&d_hup[sn * 64 + hQ * 8];
        float4 h0 = hp[0], h1 = hp[1];

        unsigned A0 = *(const unsigned*)&zS[cur][ar][ak];
        unsigned A1 = *(const unsigned*)&zS[cur][ar + 8][ak];
        unsigned A2 = *(const unsigned*)&zS[cur][ar][ak + 8];
        unsigned A3 = *(const unsigned*)&zS[cur][ar + 8][ak + 8];
#pragma unroll
        for (int q = 0; q < 18; q++) {
            int cb = (w * 18 + q) * 8;
            float c0 = 0.f, c1 = 0.f, c2 = 0.f, c3 = 0.f;
            mma16816(c0, c1, c2, c3, A0, A1, A2, A3, Bf0[q], Bf1[q]);
            int cg0 = cb + 2 * (lane & 3);
            *(float2*)&tpwS[ar][cg0]     = make_float2(c0, c1);
            *(float2*)&tpwS[ar + 8][cg0] = make_float2(c2, c3);
        }
        *(float4*)&hupS[hE][hQ * 8] = h0;
        *(float4*)&hupS[hE][hQ * 8 + 4] = h1;
        if (hasNext) {
            if (tid < 32)      *(uint4*)&zS[nxt][zE][zP * 8] = zreg;
            else if (tid < 80) *(float4*)&shS[nxt][shE][shP * 4] = shreg;
            else if (tid < 96) sndS[nxt][snE] = snreg;
        }
        __syncthreads();

        for (int e = 0; e < cnt; e++) {
            int i = base + e;
            while (i >= nextb) {
#pragma unroll
                for (int j = 0; j < SCNT; j++)
                    d_aggh[(long)(n0 + kn) * 576 + c * 9 + SOFF + j] =
                        __float2half(acc[j] * (1.0f / 32.0f));
#pragma unroll
                for (int j = 0; j < SCNT; j++) acc[j] = 0.f;
                kn++;
                nextb = (kn < NPB) ? offsS[kn + 1] : 0x7fffffff;
            }
            float hv = hupS[e][c];
#pragma unroll
            for (int j = 0; j < SCNT; j++)
                acc[j] = fmaf(hv * shS[cur][e][SOFF + j], tpwS[e][c * 9 + SOFF + j], acc[j]);
        }
        __syncthreads();
        cur = nxt;
    }
    while (kn < NPB) {
#pragma unroll
        for (int j = 0; j < SCNT; j++)
            d_aggh[(long)(n0 + kn) * 576 + c * 9 + SOFF + j] =
                __float2half(acc[j] * (1.0f / 32.0f));
#pragma unroll
        for (int j = 0; j < SCNT; j++) acc[j] = 0.f;
        kn++;
    }
}

__global__ __launch_bounds__(128) void k_agg(int t) {
    __shared__ float tpwS[16][TPW_PAD];
    __shared__ float hupS[16][64];
    __shared__ __half zS[2][16][16];
    __shared__ float shS[2][16][12];
    __shared__ int sndS[2][16];
    __shared__ int offsS[NPB + 1];
    int tid = threadIdx.x, lane = tid & 31, w = tid >> 5;
    int n0 = blockIdx.x * NPB;
    if (tid < NPB + 1) offsS[tid] = d_offs[n0 + tid];

    const __half* W2 = d_W2T[t];
    unsigned Bf0[18], Bf1[18];
    int ar = lane >> 2, ak = (lane & 3) * 2;
#pragma unroll
    for (int q = 0; q < 18; q++) {
        int cb = (w * 18 + q) * 8;
        Bf0[q] = *(const unsigned*)&W2[(cb + ar) * 16 + ak];
        Bf1[q] = *(const unsigned*)&W2[(cb + ar) * 16 + ak + 8];
    }
    __syncthreads();
    const __half* zg = d_zh[t];
    int c = tid & 63;
    if (tid < 64) agg_core<0, 5>(tid, c, n0, zg, Bf0, Bf1, tpwS, hupS, zS, shS, sndS, offsS);
    else          agg_core<5, 4>(tid, c, n0, zg, Bf0, Bf1, tpwS, hupS, zS, shS, sndS, offsS);
}

// ---------------- update: double-buffered fp16 MMA GEMM + fused epilogues ----------------
__global__ __launch_bounds__(128) void k_update(int t, const float* __restrict__ wread,
                                                const float* __restrict__ Wmlp1,
                                                const float* __restrict__ wmlp2,
                                                float* __restrict__ out) {
    __shared__ __half As[2][64][16];
    __shared__ __half BsT[2][64][16];
    __shared__ __half hS[64][72];
    __shared__ __half WuS[64 * 64];
    int tid = threadIdx.x, lane = tid & 31, w = tid >> 5;
    int m0 = blockIdx.x * 64;
    float C[8][4];
#pragma unroll
    for (int j = 0; j < 8; j++)
#pragma unroll
        for (int i = 0; i < 4; i++) C[j][i] = 0.f;

    int r = tid >> 1, hf = tid & 1;
    int node = m0 + r;
    int arf = 16 * w + (lane >> 2), akf = (lane & 3) * 2;

    {
        uint4 av = make_uint4(0, 0, 0, 0);
        if (node < NN) av = ((const uint4*)&d_aggh[(long)node * 576])[hf];
        uint4 bv = ((const uint4*)&d_BT[t][r * 640])[hf];
        *(uint4*)&As[0][r][hf * 8] = av;
        *(uint4*)&BsT[0][r][hf * 8] = bv;
    }
    __syncthreads();

    int cur = 0;
    for (int step = 0; step < 40; step++) {
        uint4 av, bv;
        bool hasNext = (step < 39);
        if (hasNext) {
            int k0 = (step + 1) * 16;
            av = make_uint4(0, 0, 0, 0);
            if (node < NN) {
                const uint4* ap = (k0 < 576) ? (const uint4*)&d_aggh[(long)node * 576 + k0]
                                             : (const uint4*)&d_hh[node * 64 + (k0 - 576)];
                av = ap[hf];
            }
            bv = *((const uint4*)&d_BT[t][r * 640 + k0] + hf);
        }
        unsigned A0 = *(const unsigned*)&As[cur][arf][akf];
        unsigned A1 = *(const unsigned*)&As[cur][arf + 8][akf];
        unsigned A2 = *(const unsigned*)&As[cur][arf][akf + 8];
        unsigned A3 = *(const unsigned*)&As[cur][arf + 8][akf + 8];
#pragma unroll
        for (int j = 0; j < 8; j++) {
            int bn = j * 8 + (lane >> 2);
            unsigned B0 = *(const unsigned*)&BsT[cur][bn][akf];
            unsigned B1 = *(const unsigned*)&BsT[cur][bn][akf + 8];
            mma16816(C[j][0], C[j][1], C[j][2], C[j][3], A0, A1, A2, A3, B0, B1);
        }
        if (hasNext) {
            *(uint4*)&As[cur ^ 1][r][hf * 8] = av;
            *(uint4*)&BsT[cur ^ 1][r][hf * 8] = bv;
            __syncthreads();
            cur ^= 1;
        }
    }
    __syncthreads();
    {
        int ac = 2 * (lane & 3);
#pragma unroll
        for (int j = 0; j < 8; j++) {
            *(__half2*)&hS[arf][j * 8 + ac]     = __floats2half2_rn(C[j][0], C[j][1]);
            *(__half2*)&hS[arf + 8][j * 8 + ac] = __floats2half2_rn(C[j][2], C[j][3]);
        }
    }

    if (t == 0) {
        __syncthreads();
        for (int i = tid; i < 64 * 32; i += 128) {
            int rr = i >> 5, cc2 = i & 31;
            if (m0 + rr < NN)
                ((__half2*)&d_hh[(m0 + rr) * 64])[cc2] = *(__half2*)&hS[rr][cc2 * 2];
        }
        if (tid < 64 && m0 + tid < NN) {
            float acc = 0.f;
#pragma unroll
            for (int k2 = 0; k2 < 64; k2++)
                acc = fmaf(__half2float(hS[tid][k2]), wread[k2], acc);
            out[NN + m0 + tid] = acc;
        }
        {
            const uint4* src = (const uint4*)d_WupT;
            uint4* dst = (uint4*)WuS;
#pragma unroll
            for (int i = 0; i < 4; i++) dst[tid + i * 128] = src[tid + i * 128];
        }
        __syncthreads();
        float H[8][4];
#pragma unroll
        for (int j = 0; j < 8; j++)
#pragma unroll
            for (int i = 0; i < 4; i++) H[j][i] = 0.f;
#pragma unroll
        for (int s = 0; s < 4; s++) {
            int k0 = s * 16;
            unsigned A0 = *(const unsigned*)&hS[arf][k0 + akf];
            unsigned A1 = *(const unsigned*)&hS[arf + 8][k0 + akf];
            unsigned A2 = *(const unsigned*)&hS[arf][k0 + akf + 8];
            unsigned A3 = *(const unsigned*)&hS[arf + 8][k0 + akf + 8];
#pragma unroll
            for (int j = 0; j < 8; j++) {
                int bn = j * 8 + (lane >> 2);
                unsigned B0 = *(const unsigned*)&WuS[bn * 64 + k0 + akf];
                unsigned B1 = *(const unsigned*)&WuS[bn * 64 + k0 + akf + 8];
                mma16816(H[j][0], H[j][1], H[j][2], H[j][3], A0, A1, A2, A3, B0, B1);
            }
        }
        int ac = 2 * (lane & 3);
#pragma unroll
        for (int j = 0; j < 8; j++) {
            int col = j * 8 + ac;
            if (m0 + arf < NN) {
                d_hup[(m0 + arf) * 64 + col] = H[j][0];
                d_hup[(m0 + arf) * 64 + col + 1] = H[j][1];
            }
            if (m0 + arf + 8 < NN) {
                d_hup[(m0 + arf + 8) * 64 + col] = H[j][2];
                d_hup[(m0 + arf + 8) * 64 + col + 1] = H[j][3];
            }
        }
    } else {
        // stage W_mlp1 (1024 floats) into WuS (8KB) as float
        float* WmS = (float*)WuS;
        for (int i = tid; i < 1024; i += 128) WmS[i] = Wmlp1[i];
        __syncthreads();
        int nd = tid >> 1, hf2 = tid & 1;
        float y[8];
#pragma unroll
        for (int o = 0; o < 8; o++) y[o] = 0.f;
        for (int k2 = 0; k2 < 64; k2++) {
            float hv = __half2float(hS[nd][k2]);
#pragma unroll
            for (int o = 0; o < 8; o++)
                y[o] = fmaf(hv, WmS[k2 * 16 + hf2 * 8 + o], y[o]);
        }
        float acc = 0.f;
#pragma unroll
        for (int o = 0; o < 8; o++) {
            float s2 = __fdividef(y[o], 1.0f + __expf(-y[o]));
            acc = fmaf(s2, wmlp2[hf2 * 8 + o], acc);
        }
        acc += __shfl_xor_sync(0xffffffffu, acc, 1);
        if (hf2 == 0 && m0 + nd < NN) out[2 * NN + m0 + nd] = acc;
    }
}

// ---------------- host launch ----------------
extern "C" void kernel_launch(void* const* d_in, const int* in_sizes, int n_in,
                              void* d_out, int out_size) {
    const float *positions = nullptr, *node_attrs = nullptr, *shifts = nullptr;
    const float *atomic_energies = nullptr, *W_embed = nullptr, *W_up = nullptr;
    const float *W_r1 = nullptr, *W_r2 = nullptr, *W_mix = nullptr, *W_self = nullptr;
    const float *w_read = nullptr, *W_mlp1 = nullptr, *w_mlp2 = nullptr;
    const int* edge_index = nullptr;
    for (int i = 0; i < n_in; i++) {
        switch (in_sizes[i]) {
            case 30000:  positions = (const float*)d_in[i]; break;
            case 100000: node_attrs = (const float*)d_in[i]; break;
            case 480000: shifts = (const float*)d_in[i]; break;
            case 320000: edge_index = (const int*)d_in[i]; break;
            case 10:     atomic_energies = (const float*)d_in[i]; break;
            case 640:    W_embed = (const float*)d_in[i]; break;
            case 8192:   if (!W_up) W_up = (const float*)d_in[i];
                         else W_self = (const float*)d_in[i]; break;
            case 256:    W_r1 = (const float*)d_in[i]; break;
            case 18432:  W_r2 = (const float*)d_in[i]; break;
            case 73728:  W_mix = (const float*)d_in[i]; break;
            case 64:     w_read = (const float*)d_in[i]; break;
            case 1024:   W_mlp1 = (const float*)d_in[i]; break;
            case 16:     w_mlp2 = (const float*)d_in[i]; break;
            default: break;
        }
    }
    float* out = (float*)d_out;
    (void)out_size;

    k_setup<<<SETUP_BLKS, 128>>>(positions, shifts, edge_index, node_attrs, W_embed,
                                 atomic_energies, W_up, W_mix, W_self, W_r2, out);
    k_scan<<<1, 1024>>>();
    k_scatgeo<<<(EE + 127) / 128, 128>>>(edge_index, W_r1);

    for (int t = 0; t < 2; t++) {
        k_agg<<<(NN + NPB - 1) / NPB, 128>>>(t);
        k_update<<<(NN + 63) / 64, 128>>>(t, w_read, W_mlp1, w_mlp2, out);
    }
}

// round 17
// speedup vs baseline: 1.1501x; 1.0308x over previous
#include <cuda_runtime.h>
#include <cuda_fp16.h>
#include <math.h>

#define NN 10000
#define EE 160000
#define CC 64
#define RMAXF 5.0f
#define NPB 16
#define TPW_PAD 584

#define GEOM_BLKS 1250
#define EMB_BLKS  5000
#define PREP_BLKS 672
#define SETUP_BLKS (GEOM_BLKS + EMB_BLKS + PREP_BLKS)

// ---------------- device scratch ----------------
__device__ float4 d_vec[EE];
__device__ float d_sh12[EE * 12];
__device__ __half d_zh[2][EE * 16];
__device__ unsigned char d_act[EE];
__device__ int   d_count[NN];
__device__ int   d_offs[NN + 1];
__device__ int   d_cursor[NN];
__device__ int   d_ssnd[EE];
__device__ float d_hup[NN * CC];
__device__ __half d_hh[NN * CC];
__device__ __half d_aggh[NN * 576];
__device__ __half d_W2T[2][576 * 16];
__device__ __half d_BT[2][64 * 640];
__device__ __half d_WupT[64 * 64];

__device__ __forceinline__ void mma16816(float& c0, float& c1, float& c2, float& c3,
                                         unsigned a0, unsigned a1, unsigned a2, unsigned a3,
                                         unsigned b0, unsigned b1) {
    asm volatile(
        "mma.sync.aligned.m16n8k16.row.col.f32.f16.f16.f32 "
        "{%0,%1,%2,%3},{%4,%5,%6,%7},{%8,%9},{%0,%1,%2,%3};\n"
        : "+f"(c0), "+f"(c1), "+f"(c2), "+f"(c3)
        : "r"(a0), "r"(a1), "r"(a2), "r"(a3), "r"(b0), "r"(b1));
}

// ---------------- fused setup ----------------
__device__ __forceinline__ void geom1_edge(int e, const float* __restrict__ pos,
                                           const float* __restrict__ shifts,
                                           const int* __restrict__ ei) {
    int s  = ei[e];
    int rv = ei[EE + e];
    float vx = pos[rv * 3 + 0] - pos[s * 3 + 0] + shifts[e * 3 + 0];
    float vy = pos[rv * 3 + 1] - pos[s * 3 + 1] + shifts[e * 3 + 1];
    float vz = pos[rv * 3 + 2] - pos[s * 3 + 2] + shifts[e * 3 + 2];
    float r = sqrtf(vx * vx + vy * vy + vz * vz) + 1e-9f;
    bool act = (r < RMAXF);
    d_act[e] = act ? 1 : 0;
    if (!act) return;
    atomicAdd(&d_count[rv], 1);
    d_vec[e] = make_float4(vx, vy, vz, r);
}

__global__ __launch_bounds__(128) void k_setup(const float* __restrict__ pos,
        const float* __restrict__ shifts, const int* __restrict__ ei,
        const float* __restrict__ na, const float* __restrict__ We,
        const float* __restrict__ ae, const float* __restrict__ Wup,
        const float* __restrict__ Wmix, const float* __restrict__ Wself,
        const float* __restrict__ Wr2, float* __restrict__ out) {
    int b = blockIdx.x, tid = threadIdx.x;
    if (b < GEOM_BLKS) {
        int e0 = b * 128 + tid;
        if (e0 < EE) geom1_edge(e0, pos, shifts, ei);
    } else if (b < GEOM_BLKS + EMB_BLKS) {
        __shared__ float hs[128];
        int slot = tid >> 6, c = tid & 63;
        int n = (b - GEOM_BLKS) * 2 + slot;
        float acc = 0.f;
#pragma unroll
        for (int k = 0; k < 10; k++) acc = fmaf(na[n * 10 + k], We[k * 64 + c], acc);
        hs[tid] = acc;
        d_hh[n * 64 + c] = __float2half(acc);
        if (c == 0) {
            float r = 0.f;
#pragma unroll
            for (int k = 0; k < 10; k++) r = fmaf(na[n * 10 + k], ae[k], r);
            out[n] = r;
        }
        __syncthreads();
        float hu = 0.f;
#pragma unroll
        for (int k = 0; k < 64; k++) hu = fmaf(hs[slot * 64 + k], Wup[k * 64 + c], hu);
        d_hup[n * 64 + c] = hu;
    } else {
        int i = (b - GEOM_BLKS - EMB_BLKS) * 128 + tid;
        if (i < 81920) {
            int t = i / 40960, r = i - t * 40960, n = r / 640, k = r - n * 640;
            float v = (k < 576) ? Wmix[t * 36864 + k * 64 + n]
                                : Wself[t * 4096 + (k - 576) * 64 + n];
            d_BT[t][r] = __float2half(v);
        } else if (i < 86016) {
            int q = i - 81920;
            int o = q >> 6, ii = q & 63;
            d_WupT[q] = __float2half(Wup[4096 + ii * 64 + o]);
        }
        int j = i;
        if (j < 2 * 9216) {
            int t = j / 9216, r = j - t * 9216, cg = r >> 4, m = r & 15;
            d_W2T[t][r] = __float2half(Wr2[t * 9216 + m * 576 + cg]);
        }
    }
}

// ---------------- single-kernel scan ----------------
__global__ __launch_bounds__(1024) void k_scan() {
    __shared__ int ws[32];
    __shared__ int tot_s;
    int t = threadIdx.x, lane = t & 31, w = t >> 5;
    int run = 0;
    for (int rr = 0; rr < 10; rr++) {
        int idx = rr * 1024 + t;
        int v = 0;
        if (idx < NN) { v = d_count[idx]; d_count[idx] = 0; }
        int inc = v;
#pragma unroll
        for (int o = 1; o < 32; o <<= 1) {
            int u = __shfl_up_sync(0xffffffffu, inc, o);
            if (lane >= o) inc += u;
        }
        if (lane == 31) ws[w] = inc;
        __syncthreads();
        if (w == 0) {
            int x = ws[lane];
            int xi = x;
#pragma unroll
            for (int o = 1; o < 32; o <<= 1) {
                int u = __shfl_up_sync(0xffffffffu, xi, o);
                if (lane >= o) xi += u;
            }
            ws[lane] = xi - x;
            if (lane == 31) tot_s = xi;
        }
        __syncthreads();
        int excl = run + ws[w] + inc - v;
        if (idx < NN) { d_offs[idx] = excl; d_cursor[idx] = excl; }
        run += tot_s;
        __syncthreads();
    }
    if (t == 0) d_offs[NN] = run;
}

// ---------------- fused scatter + heavy geometry ----------------
__global__ __launch_bounds__(128) void k_scatgeo(const int* __restrict__ ei,
                                                 const float* __restrict__ Wr1) {
    __shared__ float Ws[256];
    Ws[threadIdx.x] = Wr1[threadIdx.x];
    Ws[threadIdx.x + 128] = Wr1[threadIdx.x + 128];
    __syncthreads();
    int e = blockIdx.x * 128 + threadIdx.x;
    if (e >= EE || !d_act[e]) return;
    int rv = ei[EE + e];
    int p = atomicAdd(&d_cursor[rv], 1);
    d_ssnd[p] = ei[e];

    float4 v = d_vec[e];
    float r = v.w;
    float inv = __fdividef(1.0f, r);
    float ux = v.x * inv, uy = v.y * inv, uz = v.z * inv;
    const float s3 = 1.7320508075688772f, s5 = 2.2360679774997896f, s15 = 3.872983346207417f;
    float4 fA = make_float4(1.0f, s3 * ux, s3 * uy, s3 * uz);
    float4 fB = make_float4(s15 * ux * uy, s15 * uy * uz,
                            0.5f * s5 * (3.0f * uz * uz - 1.0f), s15 * ux * uz);
    float4 fC = make_float4(0.5f * s15 * (ux * ux - uy * uy), 0.f, 0.f, 0.f);
    float4* shp = (float4*)&d_sh12[(long)p * 12];
    shp[0] = fA; shp[1] = fB; shp[2] = fC;

    float xx = r * (1.0f / RMAXF);
    float th = 3.14159265358979323846f * xx;
    float s1, c1;
    __sincosf(th, &s1, &c1);
    float x2 = xx * xx;
    float x6 = x2 * x2 * x2;
    float fc = 1.0f + x6 * (-28.0f + xx * (48.0f - 21.0f * xx));
    float pref = 0.6324555320336759f * inv * fc;
    float ef[8];
    float sp = 0.0f, sc = s1, c2 = 2.0f * c1;
#pragma unroll
    for (int n = 0; n < 8; n++) {
        ef[n] = pref * sc;
        float nx = c2 * sc - sp;
        sp = sc; sc = nx;
    }
#pragma unroll
    for (int t = 0; t < 2; t++) {
        float a[16];
#pragma unroll
        for (int m = 0; m < 16; m++) {
            float acc = 0.f;
#pragma unroll
            for (int n = 0; n < 8; n++) acc = fmaf(ef[n], Ws[t * 128 + n * 16 + m], acc);
            a[m] = __fdividef(acc, 1.0f + __expf(-acc));
        }
        __half2 hz[8];
#pragma unroll
        for (int q = 0; q < 8; q++) hz[q] = __floats2half2_rn(a[2 * q], a[2 * q + 1]);
        uint4* zp = (uint4*)&d_zh[t][(long)p * 16];
        zp[0] = *(uint4*)&hz[0];
        zp[1] = *(uint4*)&hz[4];
    }
}

// ---------------- agg: pipelined MMA tp_w + scalar epilogue (round-11 best) ----------------
template<int SOFF, int SCNT>
__device__ __forceinline__ void agg_core(int tid, int c, int n0,
        const __half* __restrict__ zg,
        const unsigned* Bf0, const unsigned* Bf1,
        float (*tpwS)[TPW_PAD], float (*hupS)[64],
        __half (*zS)[16][16], float (*shS)[16][12], int (*sndS)[16],
        const int* offsS) {
    int lane = tid & 31, w = tid >> 5;
    int ar = lane >> 2, ak = (lane & 3) * 2;
    int iBeg = offsS[0], iEnd = offsS[NPB];
    int nChunks = (iEnd - iBeg + 15) >> 4;
    int kn = 0, nextb = offsS[1];
    float acc[SCNT];
#pragma unroll
    for (int j = 0; j < SCNT; j++) acc[j] = 0.f;

    int zE = tid >> 1, zP = tid & 1;
    int shI = tid - 32, shE = shI / 3, shP = shI - shE * 3;
    int snE = tid - 80;
    int hE = tid >> 3, hQ = tid & 7;

    if (nChunks > 0) {
        long basec = iBeg;
        if (tid < 32) {
            long idx = basec + zE; if (idx > iEnd - 1) idx = iEnd - 1;
            *(uint4*)&zS[0][zE][zP * 8] = *(const uint4*)&zg[idx * 16 + zP * 8];
        } else if (tid < 80) {
            long idx = basec + shE; if (idx > iEnd - 1) idx = iEnd - 1;
            *(float4*)&shS[0][shE][shP * 4] = *(const float4*)&d_sh12[idx * 12 + shP * 4];
        } else if (tid < 96) {
            long idx = basec + snE; if (idx > iEnd - 1) idx = iEnd - 1;
            sndS[0][snE] = d_ssnd[idx];
        }
    }
    __syncthreads();

    int cur = 0;
    for (int k = 0; k < nChunks; k++) {
        int base = iBeg + k * 16;
        int cnt = min(16, iEnd - base);
        int nxt = cur ^ 1;
        uint4 zreg; float4 shreg; int snreg = 0;
        bool hasNext = (k + 1 < nChunks);
        if (hasNext) {
            long b2 = base + 16;
            if (tid < 32) {
                long idx = b2 + zE; if (idx > iEnd - 1) idx = iEnd - 1;
                zreg = *(const uint4*)&zg[idx * 16 + zP * 8];
            } else if (tid < 80) {
                long idx = b2 + shE; if (idx > iEnd - 1) idx = iEnd - 1;
                shreg = *(const float4*)&d_sh12[idx * 12 + shP * 4];
            } else if (tid < 96) {
                long idx = b2 + snE; if (idx > iEnd - 1) idx = iEnd - 1;
                snreg = d_ssnd[idx];
            }
        }
        int sn = (hE < cnt) ? sndS[cur][hE] : 0;
        const float4* hp = (const float4*)&d_hup[sn * 64 + hQ * 8];
        float4 h0 = hp[0], h1 = hp[1];

        unsigned A0 = *(const unsigned*)&zS[cur][ar][ak];
        unsigned A1 = *(const unsigned*)&zS[cur][ar + 8][ak];
        unsigned A2 = *(const unsigned*)&zS[cur][ar][ak + 8];
        unsigned A3 = *(const unsigned*)&zS[cur][ar + 8][ak + 8];
#pragma unroll
        for (int q = 0; q < 18; q++) {
            int cb = (w * 18 + q) * 8;
            float c0 = 0.f, c1 = 0.f, c2 = 0.f, c3 = 0.f;
            mma16816(c0, c1, c2, c3, A0, A1, A2, A3, Bf0[q], Bf1[q]);
            int cg0 = cb + 2 * (lane & 3);
            *(float2*)&tpwS[ar][cg0]     = make_float2(c0, c1);
            *(float2*)&tpwS[ar + 8][cg0] = make_float2(c2, c3);
        }
        *(float4*)&hupS[hE][hQ * 8] = h0;
        *(float4*)&hupS[hE][hQ * 8 + 4] = h1;
        if (hasNext) {
            if (tid < 32)      *(uint4*)&zS[nxt][zE][zP * 8] = zreg;
            else if (tid < 80) *(float4*)&shS[nxt][shE][shP * 4] = shreg;
            else if (tid < 96) sndS[nxt][snE] = snreg;
        }
        __syncthreads();

        for (int e = 0; e < cnt; e++) {
            int i = base + e;
            while (i >= nextb) {
#pragma unroll
                for (int j = 0; j < SCNT; j++)
                    d_aggh[(long)(n0 + kn) * 576 + c * 9 + SOFF + j] =
                        __float2half(acc[j] * (1.0f / 32.0f));
#pragma unroll
                for (int j = 0; j < SCNT; j++) acc[j] = 0.f;
                kn++;
                nextb = (kn < NPB) ? offsS[kn + 1] : 0x7fffffff;
            }
            float hv = hupS[e][c];
#pragma unroll
            for (int j = 0; j < SCNT; j++)
                acc[j] = fmaf(hv * shS[cur][e][SOFF + j], tpwS[e][c * 9 + SOFF + j], acc[j]);
        }
        __syncthreads();
        cur = nxt;
    }
    while (kn < NPB) {
#pragma unroll
        for (int j = 0; j < SCNT; j++)
            d_aggh[(long)(n0 + kn) * 576 + c * 9 + SOFF + j] =
                __float2half(acc[j] * (1.0f / 32.0f));
#pragma unroll
        for (int j = 0; j < SCNT; j++) acc[j] = 0.f;
        kn++;
    }
}

__global__ __launch_bounds__(128) void k_agg(int t) {
    __shared__ float tpwS[16][TPW_PAD];
    __shared__ float hupS[16][64];
    __shared__ __half zS[2][16][16];
    __shared__ float shS[2][16][12];
    __shared__ int sndS[2][16];
    __shared__ int offsS[NPB + 1];
    int tid = threadIdx.x, lane = tid & 31, w = tid >> 5;
    int n0 = blockIdx.x * NPB;
    if (tid < NPB + 1) offsS[tid] = d_offs[n0 + tid];

    const __half* W2 = d_W2T[t];
    unsigned Bf0[18], Bf1[18];
    int ar = lane >> 2, ak = (lane & 3) * 2;
#pragma unroll
    for (int q = 0; q < 18; q++) {
        int cb = (w * 18 + q) * 8;
        Bf0[q] = *(const unsigned*)&W2[(cb + ar) * 16 + ak];
        Bf1[q] = *(const unsigned*)&W2[(cb + ar) * 16 + ak + 8];
    }
    __syncthreads();
    const __half* zg = d_zh[t];
    int c = tid & 63;
    if (tid < 64) agg_core<0, 5>(tid, c, n0, zg, Bf0, Bf1, tpwS, hupS, zS, shS, sndS, offsS);
    else          agg_core<5, 4>(tid, c, n0, zg, Bf0, Bf1, tpwS, hupS, zS, shS, sndS, offsS);
}

// ---------------- update: double-buffered fp16 MMA GEMM + fused epilogues ----------------
__global__ __launch_bounds__(128) void k_update(int t, const float* __restrict__ wread,
                                                const float* __restrict__ Wmlp1,
                                                const float* __restrict__ wmlp2,
                                                float* __restrict__ out) {
    __shared__ __half As[2][64][16];
    __shared__ __half BsT[2][64][16];
    __shared__ __half hS[64][72];
    __shared__ __half WuS[64 * 64];
    int tid = threadIdx.x, lane = tid & 31, w = tid >> 5;
    int m0 = blockIdx.x * 64;
    float C[8][4];
#pragma unroll
    for (int j = 0; j < 8; j++)
#pragma unroll
        for (int i = 0; i < 4; i++) C[j][i] = 0.f;

    int r = tid >> 1, hf = tid & 1;
    int node = m0 + r;
    int arf = 16 * w + (lane >> 2), akf = (lane & 3) * 2;

    {
        uint4 av = make_uint4(0, 0, 0, 0);
        if (node < NN) av = ((const uint4*)&d_aggh[(long)node * 576])[hf];
        uint4 bv = ((const uint4*)&d_BT[t][r * 640])[hf];
        *(uint4*)&As[0][r][hf * 8] = av;
        *(uint4*)&BsT[0][r][hf * 8] = bv;
    }
    __syncthreads();

    int cur = 0;
    for (int step = 0; step < 40; step++) {
        uint4 av, bv;
        bool hasNext = (step < 39);
        if (hasNext) {
            int k0 = (step + 1) * 16;
            av = make_uint4(0, 0, 0, 0);
            if (node < NN) {
                const uint4* ap = (k0 < 576) ? (const uint4*)&d_aggh[(long)node * 576 + k0]
                                             : (const uint4*)&d_hh[node * 64 + (k0 - 576)];
                av = ap[hf];
            }
            bv = *((const uint4*)&d_BT[t][r * 640 + k0] + hf);
        }
        unsigned A0 = *(const unsigned*)&As[cur][arf][akf];
        unsigned A1 = *(const unsigned*)&As[cur][arf + 8][akf];
        unsigned A2 = *(const unsigned*)&As[cur][arf][akf + 8];
        unsigned A3 = *(const unsigned*)&As[cur][arf + 8][akf + 8];
#pragma unroll
        for (int j = 0; j < 8; j++) {
            int bn = j * 8 + (lane >> 2);
            unsigned B0 = *(const unsigned*)&BsT[cur][bn][akf];
            unsigned B1 = *(const unsigned*)&BsT[cur][bn][akf + 8];
            mma16816(C[j][0], C[j][1], C[j][2], C[j][3], A0, A1, A2, A3, B0, B1);
        }
        if (hasNext) {
            *(uint4*)&As[cur ^ 1][r][hf * 8] = av;
            *(uint4*)&BsT[cur ^ 1][r][hf * 8] = bv;
            __syncthreads();
            cur ^= 1;
        }
    }
    __syncthreads();
    {
        int ac = 2 * (lane & 3);
#pragma unroll
        for (int j = 0; j < 8; j++) {
            *(__half2*)&hS[arf][j * 8 + ac]     = __floats2half2_rn(C[j][0], C[j][1]);
            *(__half2*)&hS[arf + 8][j * 8 + ac] = __floats2half2_rn(C[j][2], C[j][3]);
        }
    }
    __syncthreads();

    if (t == 0) {
        for (int i = tid; i < 64 * 32; i += 128) {
            int rr = i >> 5, cc2 = i & 31;
            if (m0 + rr < NN)
                ((__half2*)&d_hh[(m0 + rr) * 64])[cc2] = *(__half2*)&hS[rr][cc2 * 2];
        }
        if (tid < 64 && m0 + tid < NN) {
            float acc = 0.f;
#pragma unroll
            for (int k2 = 0; k2 < 64; k2++)
                acc = fmaf(__half2float(hS[tid][k2]), wread[k2], acc);
            out[NN + m0 + tid] = acc;
        }
        {
            const uint4* src = (const uint4*)d_WupT;
            uint4* dst = (uint4*)WuS;
#pragma unroll
            for (int i = 0; i < 4; i++) dst[tid + i * 128] = src[tid + i * 128];
        }
        __syncthreads();
        float H[8][4];
#pragma unroll
        for (int j = 0; j < 8; j++)
#pragma unroll
            for (int i = 0; i < 4; i++) H[j][i] = 0.f;
#pragma unroll
        for (int s = 0; s < 4; s++) {
            int k0 = s * 16;
            unsigned A0 = *(const unsigned*)&hS[arf][k0 + akf];
            unsigned A1 = *(const unsigned*)&hS[arf + 8][k0 + akf];
            unsigned A2 = *(const unsigned*)&hS[arf][k0 + akf + 8];
            unsigned A3 = *(const unsigned*)&hS[arf + 8][k0 + akf + 8];
#pragma unroll
            for (int j = 0; j < 8; j++) {
                int bn = j * 8 + (lane >> 2);
                unsigned B0 = *(const unsigned*)&WuS[bn * 64 + k0 + akf];
                unsigned B1 = *(const unsigned*)&WuS[bn * 64 + k0 + akf + 8];
                mma16816(H[j][0], H[j][1], H[j][2], H[j][3], A0, A1, A2, A3, B0, B1);
            }
        }
        int ac = 2 * (lane & 3);
#pragma unroll
        for (int j = 0; j < 8; j++) {
            int col = j * 8 + ac;
            if (m0 + arf < NN) {
                d_hup[(m0 + arf) * 64 + col] = H[j][0];
                d_hup[(m0 + arf) * 64 + col + 1] = H[j][1];
            }
            if (m0 + arf + 8 < NN) {
                d_hup[(m0 + arf + 8) * 64 + col] = H[j][2];
                d_hup[(m0 + arf + 8) * 64 + col + 1] = H[j][3];
            }
        }
    } else {
        int nd = tid >> 1, hf2 = tid & 1;
        float y[8];
#pragma unroll
        for (int o = 0; o < 8; o++) y[o] = 0.f;
        for (int k2 = 0; k2 < 64; k2++) {
            float hv = __half2float(hS[nd][k2]);
#pragma unroll
            for (int o = 0; o < 8; o++)
                y[o] = fmaf(hv, Wmlp1[k2 * 16 + hf2 * 8 + o], y[o]);
        }
        float acc = 0.f;
#pragma unroll
        for (int o = 0; o < 8; o++) {
            float s2 = __fdividef(y[o], 1.0f + __expf(-y[o]));
            acc = fmaf(s2, wmlp2[hf2 * 8 + o], acc);
        }
        acc += __shfl_xor_sync(0xffffffffu, acc, 1);
        if (hf2 == 0 && m0 + nd < NN) out[2 * NN + m0 + nd] = acc;
    }
}

// ---------------- host launch ----------------
extern "C" void kernel_launch(void* const* d_in, const int* in_sizes, int n_in,
                              void* d_out, int out_size) {
    const float *positions = nullptr, *node_attrs = nullptr, *shifts = nullptr;
    const float *atomic_energies = nullptr, *W_embed = nullptr, *W_up = nullptr;
    const float *W_r1 = nullptr, *W_r2 = nullptr, *W_mix = nullptr, *W_self = nullptr;
    const float *w_read = nullptr, *W_mlp1 = nullptr, *w_mlp2 = nullptr;
    const int* edge_index = nullptr;
    for (int i = 0; i < n_in; i++) {
        switch (in_sizes[i]) {
            case 30000:  positions = (const float*)d_in[i]; break;
            case 100000: node_attrs = (const float*)d_in[i]; break;
            case 480000: shifts = (const float*)d_in[i]; break;
            case 320000: edge_index = (const int*)d_in[i]; break;
            case 10:     atomic_energies = (const float*)d_in[i]; break;
            case 640:    W_embed = (const float*)d_in[i]; break;
            case 8192:   if (!W_up) W_up = (const float*)d_in[i];
                         else W_self = (const float*)d_in[i]; break;
            case 256:    W_r1 = (const float*)d_in[i]; break;
            case 18432:  W_r2 = (const float*)d_in[i]; break;
            case 73728:  W_mix = (const float*)d_in[i]; break;
            case 64:     w_read = (const float*)d_in[i]; break;
            case 1024:   W_mlp1 = (const float*)d_in[i]; break;
            case 16:     w_mlp2 = (const float*)d_in[i]; break;
            default: break;
        }
    }
    float* out = (float*)d_out;
    (void)out_size;

    k_setup<<<SETUP_BLKS, 128>>>(positions, shifts, edge_index, node_attrs, W_embed,
                                 atomic_energies, W_up, W_mix, W_self, W_r2, out);
    k_scan<<<1, 1024>>>();
    k_scatgeo<<<(EE + 127) / 128, 128>>>(edge_index, W_r1);

    for (int t = 0; t < 2; t++) {
        k_agg<<<(NN + NPB - 1) / NPB, 128>>>(t);
        k_update<<<(NN + 63) / 64, 128>>>(t, w_read, W_mlp1, w_mlp2, out);
    }
}